// round 1
// baseline (speedup 1.0000x reference)
#include <cuda_runtime.h>
#include <math.h>

// Problem constants
#define BATCH   4
#define SEQ     2048
#define HIDDEN  1024
#define HEADS   16
#define HDIM    64
#define MROWS   (BATCH * SEQ)          // 8192
#define NQKV    (3 * HIDDEN)           // 3072

// Scratch (device globals: allocation-free, graph-safe)
__device__ float g_q[BATCH * HEADS * SEQ * HDIM];    // [b][h][s][d], pre-scaled by 1/8
__device__ float g_k[BATCH * HEADS * SEQ * HDIM];
__device__ float g_v[BATCH * HEADS * SEQ * HDIM];
__device__ float g_ctx[MROWS * HIDDEN];              // [b][s][h*d]

// ---------------------------------------------------------------------------
// Tiled SGEMM core: 128x128 block tile, BK=16, 256 threads, 8x8 micro-tile
// ---------------------------------------------------------------------------
#define BM 128
#define BN 128
#define BK 16
#define TM 8
#define TN 8

// GEMM 1: QKV = query @ w_qkv + b_qkv, epilogue scatters into g_q/g_k/g_v
__global__ __launch_bounds__(256) void gemm_qkv_kernel(
    const float* __restrict__ A,      // [8192][1024]
    const float* __restrict__ Bw,     // [1024][3072]
    const float* __restrict__ bqkv)   // [3072]
{
    __shared__ float As[BK][BM + 4];  // transposed A tile, padded
    __shared__ float Bs[BK][BN];

    const int K = HIDDEN, N = NQKV;
    const int bm = blockIdx.y * BM;
    const int bn = blockIdx.x * BN;
    const int tid = threadIdx.x;
    const int tx = tid & 15;
    const int ty = tid >> 4;

    float acc[TM][TN];
#pragma unroll
    for (int i = 0; i < TM; i++)
#pragma unroll
        for (int j = 0; j < TN; j++) acc[i][j] = 0.f;

    for (int k0 = 0; k0 < K; k0 += BK) {
#pragma unroll
        for (int it = 0; it < 2; it++) {           // A tile: 128x16
            int id = tid + it * 256;               // 0..511 float4 slots
            int r  = id >> 2;                      // 0..127
            int c4 = (id & 3) << 2;                // 0,4,8,12
            float4 v = *reinterpret_cast<const float4*>(&A[(bm + r) * K + k0 + c4]);
            As[c4 + 0][r] = v.x; As[c4 + 1][r] = v.y;
            As[c4 + 2][r] = v.z; As[c4 + 3][r] = v.w;
        }
#pragma unroll
        for (int it = 0; it < 2; it++) {           // B tile: 16x128
            int id = tid + it * 256;
            int r  = id >> 5;                      // 0..15
            int c4 = (id & 31) << 2;               // 0..124
            *reinterpret_cast<float4*>(&Bs[r][c4]) =
                *reinterpret_cast<const float4*>(&Bw[(k0 + r) * N + bn + c4]);
        }
        __syncthreads();

#pragma unroll
        for (int kk = 0; kk < BK; kk++) {
            float a[TM], b[TN];
#pragma unroll
            for (int i = 0; i < TM; i++) a[i] = As[kk][ty * TM + i];
#pragma unroll
            for (int j = 0; j < TN; j++) b[j] = Bs[kk][tx * TN + j];
#pragma unroll
            for (int i = 0; i < TM; i++)
#pragma unroll
                for (int j = 0; j < TN; j++)
                    acc[i][j] = fmaf(a[i], b[j], acc[i][j]);
        }
        __syncthreads();
    }

    // Epilogue: bias + head-split scatter, q pre-scaled by HDIM^-0.5 = 0.125
#pragma unroll
    for (int i = 0; i < TM; i++) {
        int m = bm + ty * TM + i;
        int b = m >> 11;            // /2048
        int s = m & 2047;
#pragma unroll
        for (int j = 0; j < TN; j++) {
            int n = bn + tx * TN + j;
            float v = acc[i][j] + bqkv[n];
            int sec = n >> 10;          // 0=q 1=k 2=v
            int nn  = n & 1023;
            int h   = nn >> 6;
            int dd  = nn & 63;
            int idx = (((b * HEADS + h) * SEQ) + s) * HDIM + dd;
            if (sec == 0)      g_q[idx] = v * 0.125f;
            else if (sec == 1) g_k[idx] = v;
            else               g_v[idx] = v;
        }
    }
}

// GEMM 2: out = g_ctx @ w_o + b_o
__global__ __launch_bounds__(256) void gemm_o_kernel(
    const float* __restrict__ Bw,    // w_o [1024][1024]
    const float* __restrict__ bo,    // [1024]
    float* __restrict__ C)           // [8192][1024]
{
    __shared__ float As[BK][BM + 4];
    __shared__ float Bs[BK][BN];

    const int K = HIDDEN, N = HIDDEN;
    const int bm = blockIdx.y * BM;
    const int bn = blockIdx.x * BN;
    const int tid = threadIdx.x;
    const int tx = tid & 15;
    const int ty = tid >> 4;

    float acc[TM][TN];
#pragma unroll
    for (int i = 0; i < TM; i++)
#pragma unroll
        for (int j = 0; j < TN; j++) acc[i][j] = 0.f;

    for (int k0 = 0; k0 < K; k0 += BK) {
#pragma unroll
        for (int it = 0; it < 2; it++) {
            int id = tid + it * 256;
            int r  = id >> 2;
            int c4 = (id & 3) << 2;
            float4 v = *reinterpret_cast<const float4*>(&g_ctx[(bm + r) * K + k0 + c4]);
            As[c4 + 0][r] = v.x; As[c4 + 1][r] = v.y;
            As[c4 + 2][r] = v.z; As[c4 + 3][r] = v.w;
        }
#pragma unroll
        for (int it = 0; it < 2; it++) {
            int id = tid + it * 256;
            int r  = id >> 5;
            int c4 = (id & 31) << 2;
            *reinterpret_cast<float4*>(&Bs[r][c4]) =
                *reinterpret_cast<const float4*>(&Bw[(k0 + r) * N + bn + c4]);
        }
        __syncthreads();

#pragma unroll
        for (int kk = 0; kk < BK; kk++) {
            float a[TM], b[TN];
#pragma unroll
            for (int i = 0; i < TM; i++) a[i] = As[kk][ty * TM + i];
#pragma unroll
            for (int j = 0; j < TN; j++) b[j] = Bs[kk][tx * TN + j];
#pragma unroll
            for (int i = 0; i < TM; i++)
#pragma unroll
                for (int j = 0; j < TN; j++)
                    acc[i][j] = fmaf(a[i], b[j], acc[i][j]);
        }
        __syncthreads();
    }

#pragma unroll
    for (int i = 0; i < TM; i++) {
        int m = bm + ty * TM + i;
#pragma unroll
        for (int j = 0; j < TN; j += 4) {
            int n = bn + tx * TN + j;
            float4 v;
            v.x = acc[i][j + 0] + bo[n + 0];
            v.y = acc[i][j + 1] + bo[n + 1];
            v.z = acc[i][j + 2] + bo[n + 2];
            v.w = acc[i][j + 3] + bo[n + 3];
            *reinterpret_cast<float4*>(&C[m * N + n]) = v;
        }
    }
}

// ---------------------------------------------------------------------------
// Flash attention: Br=64, Bc=32, d=64; grid (S/64, HEADS, BATCH), 256 threads
// ---------------------------------------------------------------------------
#define FBR 64
#define FBC 32

__global__ __launch_bounds__(256) void flash_kernel(const float* __restrict__ bias)
{
    __shared__ float Qs[FBR][HDIM + 1];   // 64x65
    __shared__ float Ks[FBC][HDIM + 1];   // 32x65
    __shared__ float Vs[FBC][HDIM + 1];   // 32x65
    __shared__ float Ps[FBR][FBC + 1];    // 64x33

    const int qt = blockIdx.x;
    const int h  = blockIdx.y;
    const int b  = blockIdx.z;
    const int tid = threadIdx.x;
    const int tx = tid & 15;
    const int ty = tid >> 4;

    const float* qbase = g_q + ((b * HEADS + h) * SEQ) * HDIM;
    const float* kbase = g_k + ((b * HEADS + h) * SEQ) * HDIM;
    const float* vbase = g_v + ((b * HEADS + h) * SEQ) * HDIM;

    // load Q tile (64x64) once
#pragma unroll
    for (int it = 0; it < 4; it++) {
        int id = tid + it * 256;      // 0..1023 float4 slots
        int r  = id >> 4;             // 0..63
        int c4 = (id & 15) << 2;      // 0..60
        float4 v = *reinterpret_cast<const float4*>(&qbase[(qt * FBR + r) * HDIM + c4]);
        Qs[r][c4 + 0] = v.x; Qs[r][c4 + 1] = v.y;
        Qs[r][c4 + 2] = v.z; Qs[r][c4 + 3] = v.w;
    }

    float m_i[4], l_i[4], o[4][4];
#pragma unroll
    for (int i = 0; i < 4; i++) {
        m_i[i] = -INFINITY; l_i[i] = 0.f;
#pragma unroll
        for (int j = 0; j < 4; j++) o[i][j] = 0.f;
    }

    for (int kt = 0; kt < SEQ / FBC; kt++) {
        __syncthreads();   // prior O-update done reading Ks/Vs/Ps
#pragma unroll
        for (int it = 0; it < 2; it++) {     // K,V tiles: 32x64 each
            int id = tid + it * 256;         // 0..511 float4
            int r  = id >> 4;                // 0..31
            int c4 = (id & 15) << 2;
            float4 kv = *reinterpret_cast<const float4*>(&kbase[(kt * FBC + r) * HDIM + c4]);
            Ks[r][c4 + 0] = kv.x; Ks[r][c4 + 1] = kv.y;
            Ks[r][c4 + 2] = kv.z; Ks[r][c4 + 3] = kv.w;
            float4 vv = *reinterpret_cast<const float4*>(&vbase[(kt * FBC + r) * HDIM + c4]);
            Vs[r][c4 + 0] = vv.x; Vs[r][c4 + 1] = vv.y;
            Vs[r][c4 + 2] = vv.z; Vs[r][c4 + 3] = vv.w;
        }
        __syncthreads();

        // S = Q K^T (rows r_i = ty+16i, cols c_j = tx+16j)
        float sv[4][2];
#pragma unroll
        for (int i = 0; i < 4; i++) { sv[i][0] = 0.f; sv[i][1] = 0.f; }
#pragma unroll
        for (int kd = 0; kd < HDIM; kd++) {
            float aq[4], bk[2];
#pragma unroll
            for (int i = 0; i < 4; i++) aq[i] = Qs[ty + 16 * i][kd];
#pragma unroll
            for (int j = 0; j < 2; j++) bk[j] = Ks[tx + 16 * j][kd];
#pragma unroll
            for (int i = 0; i < 4; i++)
#pragma unroll
                for (int j = 0; j < 2; j++)
                    sv[i][j] = fmaf(aq[i], bk[j], sv[i][j]);
        }
        // + bias
#pragma unroll
        for (int i = 0; i < 4; i++) {
            int qrow = qt * FBR + ty + 16 * i;
#pragma unroll
            for (int j = 0; j < 2; j++) {
                int kcol = kt * FBC + tx + 16 * j;
                sv[i][j] += bias[qrow * SEQ + kcol];
            }
        }

        // online softmax stats (reduce across the 16 lanes sharing a row)
        float mx[4];
#pragma unroll
        for (int i = 0; i < 4; i++) {
            mx[i] = fmaxf(sv[i][0], sv[i][1]);
#pragma unroll
            for (int off = 8; off >= 1; off >>= 1)
                mx[i] = fmaxf(mx[i], __shfl_xor_sync(0xffffffffu, mx[i], off));
        }
        float alpha[4], p[4][2], ls[4];
#pragma unroll
        for (int i = 0; i < 4; i++) {
            float mn = fmaxf(m_i[i], mx[i]);
            alpha[i] = __expf(m_i[i] - mn);   // 0 when m_i = -inf
            m_i[i] = mn;
            p[i][0] = __expf(sv[i][0] - mn);
            p[i][1] = __expf(sv[i][1] - mn);
            ls[i] = p[i][0] + p[i][1];
#pragma unroll
            for (int off = 8; off >= 1; off >>= 1)
                ls[i] += __shfl_xor_sync(0xffffffffu, ls[i], off);
            l_i[i] = l_i[i] * alpha[i] + ls[i];
#pragma unroll
            for (int j = 0; j < 4; j++) o[i][j] *= alpha[i];
            Ps[ty + 16 * i][tx + 0 ] = p[i][0];
            Ps[ty + 16 * i][tx + 16] = p[i][1];
        }
        __syncthreads();

        // O += P V
#pragma unroll
        for (int kv = 0; kv < FBC; kv++) {
            float ap[4], bv[4];
#pragma unroll
            for (int i = 0; i < 4; i++) ap[i] = Ps[ty + 16 * i][kv];
#pragma unroll
            for (int j = 0; j < 4; j++) bv[j] = Vs[kv][tx + 16 * j];
#pragma unroll
            for (int i = 0; i < 4; i++)
#pragma unroll
                for (int j = 0; j < 4; j++)
                    o[i][j] = fmaf(ap[i], bv[j], o[i][j]);
        }
    }

    // epilogue: normalize, write ctx in [b][s][h][d]
#pragma unroll
    for (int i = 0; i < 4; i++) {
        float inv = 1.f / l_i[i];
        int srow = qt * FBR + ty + 16 * i;
        int base = ((b * SEQ + srow) * HEADS + h) * HDIM;
#pragma unroll
        for (int j = 0; j < 4; j++)
            g_ctx[base + tx + 16 * j] = o[i][j] * inv;
    }
}

// ---------------------------------------------------------------------------
extern "C" void kernel_launch(void* const* d_in, const int* in_sizes, int n_in,
                              void* d_out, int out_size)
{
    const float* query = (const float*)d_in[0];
    const float* bias  = (const float*)d_in[1];
    const float* w_qkv = (const float*)d_in[2];
    const float* b_qkv = (const float*)d_in[3];
    const float* w_o   = (const float*)d_in[4];
    const float* b_o   = (const float*)d_in[5];
    float* out = (float*)d_out;

    dim3 g1(NQKV / BN, MROWS / BM);        // 24 x 64
    gemm_qkv_kernel<<<g1, 256>>>(query, w_qkv, b_qkv);

    dim3 gf(SEQ / FBR, HEADS, BATCH);      // 32 x 16 x 4
    flash_kernel<<<gf, 256>>>(bias);

    dim3 g2(HIDDEN / BN, MROWS / BM);      // 8 x 64
    gemm_o_kernel<<<g2, 256>>>(w_o, b_o, out);
}

// round 2
// speedup vs baseline: 1.0002x; 1.0002x over previous
#include <cuda_runtime.h>
#include <math.h>

// Problem constants
#define BATCH   4
#define SEQ     2048
#define HIDDEN  1024
#define HEADS   16
#define HDIM    64
#define MROWS   (BATCH * SEQ)          // 8192
#define NQKV    (3 * HIDDEN)           // 3072

// Scratch (device globals: allocation-free, graph-safe)
__device__ float g_q[BATCH * HEADS * SEQ * HDIM];    // [b][h][s][d], pre-scaled by 1/8
__device__ float g_k[BATCH * HEADS * SEQ * HDIM];
__device__ float g_v[BATCH * HEADS * SEQ * HDIM];
__device__ float g_ctx[MROWS * HIDDEN];              // [b][s][h*d]

// ---------------------------------------------------------------------------
// Tiled SGEMM core: 128x128 block tile, BK=16, 256 threads, 8x8 micro-tile
// ---------------------------------------------------------------------------
#define BM 128
#define BN 128
#define BK 16
#define TM 8
#define TN 8

// GEMM 1: QKV = query @ w_qkv + b_qkv, epilogue scatters into g_q/g_k/g_v
__global__ __launch_bounds__(256) void gemm_qkv_kernel(
    const float* __restrict__ A,      // [8192][1024]
    const float* __restrict__ Bw,     // [1024][3072]
    const float* __restrict__ bqkv)   // [3072]
{
    __shared__ float As[BK][BM + 4];  // transposed A tile, padded
    __shared__ float Bs[BK][BN];

    const int K = HIDDEN, N = NQKV;
    const int bm = blockIdx.y * BM;
    const int bn = blockIdx.x * BN;
    const int tid = threadIdx.x;
    const int tx = tid & 15;
    const int ty = tid >> 4;

    float acc[TM][TN];
#pragma unroll
    for (int i = 0; i < TM; i++)
#pragma unroll
        for (int j = 0; j < TN; j++) acc[i][j] = 0.f;

    for (int k0 = 0; k0 < K; k0 += BK) {
#pragma unroll
        for (int it = 0; it < 2; it++) {           // A tile: 128x16
            int id = tid + it * 256;               // 0..511 float4 slots
            int r  = id >> 2;                      // 0..127
            int c4 = (id & 3) << 2;                // 0,4,8,12
            float4 v = *reinterpret_cast<const float4*>(&A[(bm + r) * K + k0 + c4]);
            As[c4 + 0][r] = v.x; As[c4 + 1][r] = v.y;
            As[c4 + 2][r] = v.z; As[c4 + 3][r] = v.w;
        }
#pragma unroll
        for (int it = 0; it < 2; it++) {           // B tile: 16x128
            int id = tid + it * 256;
            int r  = id >> 5;                      // 0..15
            int c4 = (id & 31) << 2;               // 0..124
            *reinterpret_cast<float4*>(&Bs[r][c4]) =
                *reinterpret_cast<const float4*>(&Bw[(k0 + r) * N + bn + c4]);
        }
        __syncthreads();

#pragma unroll
        for (int kk = 0; kk < BK; kk++) {
            float a[TM], b[TN];
#pragma unroll
            for (int i = 0; i < TM; i++) a[i] = As[kk][ty * TM + i];
#pragma unroll
            for (int j = 0; j < TN; j++) b[j] = Bs[kk][tx * TN + j];
#pragma unroll
            for (int i = 0; i < TM; i++)
#pragma unroll
                for (int j = 0; j < TN; j++)
                    acc[i][j] = fmaf(a[i], b[j], acc[i][j]);
        }
        __syncthreads();
    }

    // Epilogue: bias + head-split scatter, q pre-scaled by HDIM^-0.5 = 0.125
#pragma unroll
    for (int i = 0; i < TM; i++) {
        int m = bm + ty * TM + i;
        int b = m >> 11;            // /2048
        int s = m & 2047;
#pragma unroll
        for (int j = 0; j < TN; j++) {
            int n = bn + tx * TN + j;
            float v = acc[i][j] + bqkv[n];
            int sec = n >> 10;          // 0=q 1=k 2=v
            int nn  = n & 1023;
            int h   = nn >> 6;
            int dd  = nn & 63;
            int idx = (((b * HEADS + h) * SEQ) + s) * HDIM + dd;
            if (sec == 0)      g_q[idx] = v * 0.125f;
            else if (sec == 1) g_k[idx] = v;
            else               g_v[idx] = v;
        }
    }
}

// GEMM 2: out = g_ctx @ w_o + b_o
__global__ __launch_bounds__(256) void gemm_o_kernel(
    const float* __restrict__ Bw,    // w_o [1024][1024]
    const float* __restrict__ bo,    // [1024]
    float* __restrict__ C)           // [8192][1024]
{
    __shared__ float As[BK][BM + 4];
    __shared__ float Bs[BK][BN];

    const int K = HIDDEN, N = HIDDEN;
    const int bm = blockIdx.y * BM;
    const int bn = blockIdx.x * BN;
    const int tid = threadIdx.x;
    const int tx = tid & 15;
    const int ty = tid >> 4;

    float acc[TM][TN];
#pragma unroll
    for (int i = 0; i < TM; i++)
#pragma unroll
        for (int j = 0; j < TN; j++) acc[i][j] = 0.f;

    for (int k0 = 0; k0 < K; k0 += BK) {
#pragma unroll
        for (int it = 0; it < 2; it++) {
            int id = tid + it * 256;
            int r  = id >> 2;
            int c4 = (id & 3) << 2;
            float4 v = *reinterpret_cast<const float4*>(&g_ctx[(bm + r) * K + k0 + c4]);
            As[c4 + 0][r] = v.x; As[c4 + 1][r] = v.y;
            As[c4 + 2][r] = v.z; As[c4 + 3][r] = v.w;
        }
#pragma unroll
        for (int it = 0; it < 2; it++) {
            int id = tid + it * 256;
            int r  = id >> 5;
            int c4 = (id & 31) << 2;
            *reinterpret_cast<float4*>(&Bs[r][c4]) =
                *reinterpret_cast<const float4*>(&Bw[(k0 + r) * N + bn + c4]);
        }
        __syncthreads();

#pragma unroll
        for (int kk = 0; kk < BK; kk++) {
            float a[TM], b[TN];
#pragma unroll
            for (int i = 0; i < TM; i++) a[i] = As[kk][ty * TM + i];
#pragma unroll
            for (int j = 0; j < TN; j++) b[j] = Bs[kk][tx * TN + j];
#pragma unroll
            for (int i = 0; i < TM; i++)
#pragma unroll
                for (int j = 0; j < TN; j++)
                    acc[i][j] = fmaf(a[i], b[j], acc[i][j]);
        }
        __syncthreads();
    }

#pragma unroll
    for (int i = 0; i < TM; i++) {
        int m = bm + ty * TM + i;
#pragma unroll
        for (int j = 0; j < TN; j += 4) {
            int n = bn + tx * TN + j;
            float4 v;
            v.x = acc[i][j + 0] + bo[n + 0];
            v.y = acc[i][j + 1] + bo[n + 1];
            v.z = acc[i][j + 2] + bo[n + 2];
            v.w = acc[i][j + 3] + bo[n + 3];
            *reinterpret_cast<float4*>(&C[m * N + n]) = v;
        }
    }
}

// ---------------------------------------------------------------------------
// Flash attention: Br=64, Bc=32, d=64; grid (S/64, HEADS, BATCH), 256 threads
// ---------------------------------------------------------------------------
#define FBR 64
#define FBC 32

__global__ __launch_bounds__(256) void flash_kernel(const float* __restrict__ bias)
{
    __shared__ float Qs[FBR][HDIM + 1];   // 64x65
    __shared__ float Ks[FBC][HDIM + 1];   // 32x65
    __shared__ float Vs[FBC][HDIM + 1];   // 32x65
    __shared__ float Ps[FBR][FBC + 1];    // 64x33

    const int qt = blockIdx.x;
    const int h  = blockIdx.y;
    const int b  = blockIdx.z;
    const int tid = threadIdx.x;
    const int tx = tid & 15;
    const int ty = tid >> 4;

    const float* qbase = g_q + ((b * HEADS + h) * SEQ) * HDIM;
    const float* kbase = g_k + ((b * HEADS + h) * SEQ) * HDIM;
    const float* vbase = g_v + ((b * HEADS + h) * SEQ) * HDIM;

    // load Q tile (64x64) once
#pragma unroll
    for (int it = 0; it < 4; it++) {
        int id = tid + it * 256;      // 0..1023 float4 slots
        int r  = id >> 4;             // 0..63
        int c4 = (id & 15) << 2;      // 0..60
        float4 v = *reinterpret_cast<const float4*>(&qbase[(qt * FBR + r) * HDIM + c4]);
        Qs[r][c4 + 0] = v.x; Qs[r][c4 + 1] = v.y;
        Qs[r][c4 + 2] = v.z; Qs[r][c4 + 3] = v.w;
    }

    float m_i[4], l_i[4], o[4][4];
#pragma unroll
    for (int i = 0; i < 4; i++) {
        m_i[i] = -INFINITY; l_i[i] = 0.f;
#pragma unroll
        for (int j = 0; j < 4; j++) o[i][j] = 0.f;
    }

    for (int kt = 0; kt < SEQ / FBC; kt++) {
        __syncthreads();   // prior O-update done reading Ks/Vs/Ps
#pragma unroll
        for (int it = 0; it < 2; it++) {     // K,V tiles: 32x64 each
            int id = tid + it * 256;         // 0..511 float4
            int r  = id >> 4;                // 0..31
            int c4 = (id & 15) << 2;
            float4 kv = *reinterpret_cast<const float4*>(&kbase[(kt * FBC + r) * HDIM + c4]);
            Ks[r][c4 + 0] = kv.x; Ks[r][c4 + 1] = kv.y;
            Ks[r][c4 + 2] = kv.z; Ks[r][c4 + 3] = kv.w;
            float4 vv = *reinterpret_cast<const float4*>(&vbase[(kt * FBC + r) * HDIM + c4]);
            Vs[r][c4 + 0] = vv.x; Vs[r][c4 + 1] = vv.y;
            Vs[r][c4 + 2] = vv.z; Vs[r][c4 + 3] = vv.w;
        }
        __syncthreads();

        // S = Q K^T (rows r_i = ty+16i, cols c_j = tx+16j)
        float sv[4][2];
#pragma unroll
        for (int i = 0; i < 4; i++) { sv[i][0] = 0.f; sv[i][1] = 0.f; }
#pragma unroll
        for (int kd = 0; kd < HDIM; kd++) {
            float aq[4], bk[2];
#pragma unroll
            for (int i = 0; i < 4; i++) aq[i] = Qs[ty + 16 * i][kd];
#pragma unroll
            for (int j = 0; j < 2; j++) bk[j] = Ks[tx + 16 * j][kd];
#pragma unroll
            for (int i = 0; i < 4; i++)
#pragma unroll
                for (int j = 0; j < 2; j++)
                    sv[i][j] = fmaf(aq[i], bk[j], sv[i][j]);
        }
        // + bias
#pragma unroll
        for (int i = 0; i < 4; i++) {
            int qrow = qt * FBR + ty + 16 * i;
#pragma unroll
            for (int j = 0; j < 2; j++) {
                int kcol = kt * FBC + tx + 16 * j;
                sv[i][j] += bias[qrow * SEQ + kcol];
            }
        }

        // online softmax stats (reduce across the 16 lanes sharing a row)
        float mx[4];
#pragma unroll
        for (int i = 0; i < 4; i++) {
            mx[i] = fmaxf(sv[i][0], sv[i][1]);
#pragma unroll
            for (int off = 8; off >= 1; off >>= 1)
                mx[i] = fmaxf(mx[i], __shfl_xor_sync(0xffffffffu, mx[i], off));
        }
        float alpha[4], p[4][2], ls[4];
#pragma unroll
        for (int i = 0; i < 4; i++) {
            float mn = fmaxf(m_i[i], mx[i]);
            alpha[i] = __expf(m_i[i] - mn);   // 0 when m_i = -inf
            m_i[i] = mn;
            p[i][0] = __expf(sv[i][0] - mn);
            p[i][1] = __expf(sv[i][1] - mn);
            ls[i] = p[i][0] + p[i][1];
#pragma unroll
            for (int off = 8; off >= 1; off >>= 1)
                ls[i] += __shfl_xor_sync(0xffffffffu, ls[i], off);
            l_i[i] = l_i[i] * alpha[i] + ls[i];
#pragma unroll
            for (int j = 0; j < 4; j++) o[i][j] *= alpha[i];
            Ps[ty + 16 * i][tx + 0 ] = p[i][0];
            Ps[ty + 16 * i][tx + 16] = p[i][1];
        }
        __syncthreads();

        // O += P V
#pragma unroll
        for (int kv = 0; kv < FBC; kv++) {
            float ap[4], bv[4];
#pragma unroll
            for (int i = 0; i < 4; i++) ap[i] = Ps[ty + 16 * i][kv];
#pragma unroll
            for (int j = 0; j < 4; j++) bv[j] = Vs[kv][tx + 16 * j];
#pragma unroll
            for (int i = 0; i < 4; i++)
#pragma unroll
                for (int j = 0; j < 4; j++)
                    o[i][j] = fmaf(ap[i], bv[j], o[i][j]);
        }
    }

    // epilogue: normalize, write ctx in [b][s][h][d]
#pragma unroll
    for (int i = 0; i < 4; i++) {
        float inv = 1.f / l_i[i];
        int srow = qt * FBR + ty + 16 * i;
        int base = ((b * SEQ + srow) * HEADS + h) * HDIM;
#pragma unroll
        for (int j = 0; j < 4; j++)
            g_ctx[base + tx + 16 * j] = o[i][j] * inv;
    }
}

// ---------------------------------------------------------------------------
extern "C" void kernel_launch(void* const* d_in, const int* in_sizes, int n_in,
                              void* d_out, int out_size)
{
    const float* query = (const float*)d_in[0];
    const float* bias  = (const float*)d_in[1];
    const float* w_qkv = (const float*)d_in[2];
    const float* b_qkv = (const float*)d_in[3];
    const float* w_o   = (const float*)d_in[4];
    const float* b_o   = (const float*)d_in[5];
    float* out = (float*)d_out;

    dim3 g1(NQKV / BN, MROWS / BM);        // 24 x 64
    gemm_qkv_kernel<<<g1, 256>>>(query, w_qkv, b_qkv);

    dim3 gf(SEQ / FBR, HEADS, BATCH);      // 32 x 16 x 4
    flash_kernel<<<gf, 256>>>(bias);

    dim3 g2(HIDDEN / BN, MROWS / BM);      // 8 x 64
    gemm_o_kernel<<<g2, 256>>>(w_o, b_o, out);
}

// round 3
// speedup vs baseline: 1.0007x; 1.0005x over previous
#include <cuda_runtime.h>
#include <math.h>

// Problem constants
#define BATCH   4
#define SEQ     2048
#define HIDDEN  1024
#define HEADS   16
#define HDIM    64
#define MROWS   (BATCH * SEQ)          // 8192
#define NQKV    (3 * HIDDEN)           // 3072

// Scratch (device globals: allocation-free, graph-safe)
__device__ float g_q[BATCH * HEADS * SEQ * HDIM];    // [b][h][s][d], pre-scaled by 1/8
__device__ float g_k[BATCH * HEADS * SEQ * HDIM];
__device__ float g_v[BATCH * HEADS * SEQ * HDIM];
__device__ float g_ctx[MROWS * HIDDEN];              // [b][s][h*d]

// ---------------------------------------------------------------------------
// Tiled SGEMM core: 128x128 block tile, BK=16, 256 threads, 8x8 micro-tile
// ---------------------------------------------------------------------------
#define BM 128
#define BN 128
#define BK 16
#define TM 8
#define TN 8

// GEMM 1: QKV = query @ w_qkv + b_qkv, epilogue scatters into g_q/g_k/g_v
__global__ __launch_bounds__(256) void gemm_qkv_kernel(
    const float* __restrict__ A,      // [8192][1024]
    const float* __restrict__ Bw,     // [1024][3072]
    const float* __restrict__ bqkv)   // [3072]
{
    __shared__ float As[BK][BM + 4];  // transposed A tile, padded
    __shared__ float Bs[BK][BN];

    const int K = HIDDEN, N = NQKV;
    const int bm = blockIdx.y * BM;
    const int bn = blockIdx.x * BN;
    const int tid = threadIdx.x;
    const int tx = tid & 15;
    const int ty = tid >> 4;

    float acc[TM][TN];
#pragma unroll
    for (int i = 0; i < TM; i++)
#pragma unroll
        for (int j = 0; j < TN; j++) acc[i][j] = 0.f;

    for (int k0 = 0; k0 < K; k0 += BK) {
#pragma unroll
        for (int it = 0; it < 2; it++) {           // A tile: 128x16
            int id = tid + it * 256;               // 0..511 float4 slots
            int r  = id >> 2;                      // 0..127
            int c4 = (id & 3) << 2;                // 0,4,8,12
            float4 v = *reinterpret_cast<const float4*>(&A[(bm + r) * K + k0 + c4]);
            As[c4 + 0][r] = v.x; As[c4 + 1][r] = v.y;
            As[c4 + 2][r] = v.z; As[c4 + 3][r] = v.w;
        }
#pragma unroll
        for (int it = 0; it < 2; it++) {           // B tile: 16x128
            int id = tid + it * 256;
            int r  = id >> 5;                      // 0..15
            int c4 = (id & 31) << 2;               // 0..124
            *reinterpret_cast<float4*>(&Bs[r][c4]) =
                *reinterpret_cast<const float4*>(&Bw[(k0 + r) * N + bn + c4]);
        }
        __syncthreads();

#pragma unroll
        for (int kk = 0; kk < BK; kk++) {
            float a[TM], b[TN];
#pragma unroll
            for (int i = 0; i < TM; i++) a[i] = As[kk][ty * TM + i];
#pragma unroll
            for (int j = 0; j < TN; j++) b[j] = Bs[kk][tx * TN + j];
#pragma unroll
            for (int i = 0; i < TM; i++)
#pragma unroll
                for (int j = 0; j < TN; j++)
                    acc[i][j] = fmaf(a[i], b[j], acc[i][j]);
        }
        __syncthreads();
    }

    // Epilogue: bias + head-split scatter, q pre-scaled by HDIM^-0.5 = 0.125
#pragma unroll
    for (int i = 0; i < TM; i++) {
        int m = bm + ty * TM + i;
        int b = m >> 11;            // /2048
        int s = m & 2047;
#pragma unroll
        for (int j = 0; j < TN; j++) {
            int n = bn + tx * TN + j;
            float v = acc[i][j] + bqkv[n];
            int sec = n >> 10;          // 0=q 1=k 2=v
            int nn  = n & 1023;
            int h   = nn >> 6;
            int dd  = nn & 63;
            int idx = (((b * HEADS + h) * SEQ) + s) * HDIM + dd;
            if (sec == 0)      g_q[idx] = v * 0.125f;
            else if (sec == 1) g_k[idx] = v;
            else               g_v[idx] = v;
        }
    }
}

// GEMM 2: out = g_ctx @ w_o + b_o
__global__ __launch_bounds__(256) void gemm_o_kernel(
    const float* __restrict__ Bw,    // w_o [1024][1024]
    const float* __restrict__ bo,    // [1024]
    float* __restrict__ C)           // [8192][1024]
{
    __shared__ float As[BK][BM + 4];
    __shared__ float Bs[BK][BN];

    const int K = HIDDEN, N = HIDDEN;
    const int bm = blockIdx.y * BM;
    const int bn = blockIdx.x * BN;
    const int tid = threadIdx.x;
    const int tx = tid & 15;
    const int ty = tid >> 4;

    float acc[TM][TN];
#pragma unroll
    for (int i = 0; i < TM; i++)
#pragma unroll
        for (int j = 0; j < TN; j++) acc[i][j] = 0.f;

    for (int k0 = 0; k0 < K; k0 += BK) {
#pragma unroll
        for (int it = 0; it < 2; it++) {
            int id = tid + it * 256;
            int r  = id >> 2;
            int c4 = (id & 3) << 2;
            float4 v = *reinterpret_cast<const float4*>(&g_ctx[(bm + r) * K + k0 + c4]);
            As[c4 + 0][r] = v.x; As[c4 + 1][r] = v.y;
            As[c4 + 2][r] = v.z; As[c4 + 3][r] = v.w;
        }
#pragma unroll
        for (int it = 0; it < 2; it++) {
            int id = tid + it * 256;
            int r  = id >> 5;
            int c4 = (id & 31) << 2;
            *reinterpret_cast<float4*>(&Bs[r][c4]) =
                *reinterpret_cast<const float4*>(&Bw[(k0 + r) * N + bn + c4]);
        }
        __syncthreads();

#pragma unroll
        for (int kk = 0; kk < BK; kk++) {
            float a[TM], b[TN];
#pragma unroll
            for (int i = 0; i < TM; i++) a[i] = As[kk][ty * TM + i];
#pragma unroll
            for (int j = 0; j < TN; j++) b[j] = Bs[kk][tx * TN + j];
#pragma unroll
            for (int i = 0; i < TM; i++)
#pragma unroll
                for (int j = 0; j < TN; j++)
                    acc[i][j] = fmaf(a[i], b[j], acc[i][j]);
        }
        __syncthreads();
    }

#pragma unroll
    for (int i = 0; i < TM; i++) {
        int m = bm + ty * TM + i;
#pragma unroll
        for (int j = 0; j < TN; j += 4) {
            int n = bn + tx * TN + j;
            float4 v;
            v.x = acc[i][j + 0] + bo[n + 0];
            v.y = acc[i][j + 1] + bo[n + 1];
            v.z = acc[i][j + 2] + bo[n + 2];
            v.w = acc[i][j + 3] + bo[n + 3];
            *reinterpret_cast<float4*>(&C[m * N + n]) = v;
        }
    }
}

// ---------------------------------------------------------------------------
// Flash attention: Br=64, Bc=32, d=64; grid (S/64, HEADS, BATCH), 256 threads
// ---------------------------------------------------------------------------
#define FBR 64
#define FBC 32

__global__ __launch_bounds__(256) void flash_kernel(const float* __restrict__ bias)
{
    __shared__ float Qs[FBR][HDIM + 1];   // 64x65
    __shared__ float Ks[FBC][HDIM + 1];   // 32x65
    __shared__ float Vs[FBC][HDIM + 1];   // 32x65
    __shared__ float Ps[FBR][FBC + 1];    // 64x33

    const int qt = blockIdx.x;
    const int h  = blockIdx.y;
    const int b  = blockIdx.z;
    const int tid = threadIdx.x;
    const int tx = tid & 15;
    const int ty = tid >> 4;

    const float* qbase = g_q + ((b * HEADS + h) * SEQ) * HDIM;
    const float* kbase = g_k + ((b * HEADS + h) * SEQ) * HDIM;
    const float* vbase = g_v + ((b * HEADS + h) * SEQ) * HDIM;

    // load Q tile (64x64) once
#pragma unroll
    for (int it = 0; it < 4; it++) {
        int id = tid + it * 256;      // 0..1023 float4 slots
        int r  = id >> 4;             // 0..63
        int c4 = (id & 15) << 2;      // 0..60
        float4 v = *reinterpret_cast<const float4*>(&qbase[(qt * FBR + r) * HDIM + c4]);
        Qs[r][c4 + 0] = v.x; Qs[r][c4 + 1] = v.y;
        Qs[r][c4 + 2] = v.z; Qs[r][c4 + 3] = v.w;
    }

    float m_i[4], l_i[4], o[4][4];
#pragma unroll
    for (int i = 0; i < 4; i++) {
        m_i[i] = -INFINITY; l_i[i] = 0.f;
#pragma unroll
        for (int j = 0; j < 4; j++) o[i][j] = 0.f;
    }

    for (int kt = 0; kt < SEQ / FBC; kt++) {
        __syncthreads();   // prior O-update done reading Ks/Vs/Ps
#pragma unroll
        for (int it = 0; it < 2; it++) {     // K,V tiles: 32x64 each
            int id = tid + it * 256;         // 0..511 float4
            int r  = id >> 4;                // 0..31
            int c4 = (id & 15) << 2;
            float4 kv = *reinterpret_cast<const float4*>(&kbase[(kt * FBC + r) * HDIM + c4]);
            Ks[r][c4 + 0] = kv.x; Ks[r][c4 + 1] = kv.y;
            Ks[r][c4 + 2] = kv.z; Ks[r][c4 + 3] = kv.w;
            float4 vv = *reinterpret_cast<const float4*>(&vbase[(kt * FBC + r) * HDIM + c4]);
            Vs[r][c4 + 0] = vv.x; Vs[r][c4 + 1] = vv.y;
            Vs[r][c4 + 2] = vv.z; Vs[r][c4 + 3] = vv.w;
        }
        __syncthreads();

        // S = Q K^T (rows r_i = ty+16i, cols c_j = tx+16j)
        float sv[4][2];
#pragma unroll
        for (int i = 0; i < 4; i++) { sv[i][0] = 0.f; sv[i][1] = 0.f; }
#pragma unroll
        for (int kd = 0; kd < HDIM; kd++) {
            float aq[4], bk[2];
#pragma unroll
            for (int i = 0; i < 4; i++) aq[i] = Qs[ty + 16 * i][kd];
#pragma unroll
            for (int j = 0; j < 2; j++) bk[j] = Ks[tx + 16 * j][kd];
#pragma unroll
            for (int i = 0; i < 4; i++)
#pragma unroll
                for (int j = 0; j < 2; j++)
                    sv[i][j] = fmaf(aq[i], bk[j], sv[i][j]);
        }
        // + bias
#pragma unroll
        for (int i = 0; i < 4; i++) {
            int qrow = qt * FBR + ty + 16 * i;
#pragma unroll
            for (int j = 0; j < 2; j++) {
                int kcol = kt * FBC + tx + 16 * j;
                sv[i][j] += bias[qrow * SEQ + kcol];
            }
        }

        // online softmax stats (reduce across the 16 lanes sharing a row)
        float mx[4];
#pragma unroll
        for (int i = 0; i < 4; i++) {
            mx[i] = fmaxf(sv[i][0], sv[i][1]);
#pragma unroll
            for (int off = 8; off >= 1; off >>= 1)
                mx[i] = fmaxf(mx[i], __shfl_xor_sync(0xffffffffu, mx[i], off));
        }
        float alpha[4], p[4][2], ls[4];
#pragma unroll
        for (int i = 0; i < 4; i++) {
            float mn = fmaxf(m_i[i], mx[i]);
            alpha[i] = __expf(m_i[i] - mn);   // 0 when m_i = -inf
            m_i[i] = mn;
            p[i][0] = __expf(sv[i][0] - mn);
            p[i][1] = __expf(sv[i][1] - mn);
            ls[i] = p[i][0] + p[i][1];
#pragma unroll
            for (int off = 8; off >= 1; off >>= 1)
                ls[i] += __shfl_xor_sync(0xffffffffu, ls[i], off);
            l_i[i] = l_i[i] * alpha[i] + ls[i];
#pragma unroll
            for (int j = 0; j < 4; j++) o[i][j] *= alpha[i];
            Ps[ty + 16 * i][tx + 0 ] = p[i][0];
            Ps[ty + 16 * i][tx + 16] = p[i][1];
        }
        __syncthreads();

        // O += P V
#pragma unroll
        for (int kv = 0; kv < FBC; kv++) {
            float ap[4], bv[4];
#pragma unroll
            for (int i = 0; i < 4; i++) ap[i] = Ps[ty + 16 * i][kv];
#pragma unroll
            for (int j = 0; j < 4; j++) bv[j] = Vs[kv][tx + 16 * j];
#pragma unroll
            for (int i = 0; i < 4; i++)
#pragma unroll
                for (int j = 0; j < 4; j++)
                    o[i][j] = fmaf(ap[i], bv[j], o[i][j]);
        }
    }

    // epilogue: normalize, write ctx in [b][s][h][d]
#pragma unroll
    for (int i = 0; i < 4; i++) {
        float inv = 1.f / l_i[i];
        int srow = qt * FBR + ty + 16 * i;
        int base = ((b * SEQ + srow) * HEADS + h) * HDIM;
#pragma unroll
        for (int j = 0; j < 4; j++)
            g_ctx[base + tx + 16 * j] = o[i][j] * inv;
    }
}

// ---------------------------------------------------------------------------
extern "C" void kernel_launch(void* const* d_in, const int* in_sizes, int n_in,
                              void* d_out, int out_size)
{
    const float* query = (const float*)d_in[0];
    const float* bias  = (const float*)d_in[1];
    const float* w_qkv = (const float*)d_in[2];
    const float* b_qkv = (const float*)d_in[3];
    const float* w_o   = (const float*)d_in[4];
    const float* b_o   = (const float*)d_in[5];
    float* out = (float*)d_out;

    dim3 g1(NQKV / BN, MROWS / BM);        // 24 x 64
    gemm_qkv_kernel<<<g1, 256>>>(query, w_qkv, b_qkv);

    dim3 gf(SEQ / FBR, HEADS, BATCH);      // 32 x 16 x 4
    flash_kernel<<<gf, 256>>>(bias);

    dim3 g2(HIDDEN / BN, MROWS / BM);      // 8 x 64
    gemm_o_kernel<<<g2, 256>>>(w_o, b_o, out);
}

// round 4
// speedup vs baseline: 1.9382x; 1.9368x over previous
#include <cuda_runtime.h>
#include <math.h>

// Problem constants
#define BATCH   4
#define SEQ     2048
#define HIDDEN  1024
#define HEADS   16
#define HDIM    64
#define MROWS   (BATCH * SEQ)          // 8192
#define NQKV    (3 * HIDDEN)           // 3072

// Scratch (device globals: allocation-free, graph-safe)
__device__ float g_q[BATCH * HEADS * SEQ * HDIM];    // [b][h][s][d], pre-scaled by 1/8
__device__ float g_k[BATCH * HEADS * SEQ * HDIM];
__device__ float g_v[BATCH * HEADS * SEQ * HDIM];
__device__ float g_ctx[MROWS * HIDDEN];              // [b][s][h*d]

// ---------------------------------------------------------------------------
// TF32 helpers
// ---------------------------------------------------------------------------
__device__ __forceinline__ unsigned f2tf(float f) {
    unsigned u;
    asm("cvt.rna.tf32.f32 %0, %1;" : "=r"(u) : "f"(f));
    return u;
}

// hi/lo error-free split: v ~= hi + lo, both tf32-representable
__device__ __forceinline__ void cvt4(uint4& h, uint4& l, float4 v) {
    h.x = f2tf(v.x); l.x = f2tf(v.x - __uint_as_float(h.x));
    h.y = f2tf(v.y); l.y = f2tf(v.y - __uint_as_float(h.y));
    h.z = f2tf(v.z); l.z = f2tf(v.z - __uint_as_float(h.z));
    h.w = f2tf(v.w); l.w = f2tf(v.w - __uint_as_float(h.w));
}
__device__ __forceinline__ uint4 cvt4s(float4 v) {
    uint4 h;
    h.x = f2tf(v.x); h.y = f2tf(v.y); h.z = f2tf(v.z); h.w = f2tf(v.w);
    return h;
}

// D += A(m16k8) * B(k8n8), tf32 inputs, f32 accum
__device__ __forceinline__ void mma8(float* d, const unsigned* a, const unsigned* b) {
    asm volatile(
        "mma.sync.aligned.m16n8k8.row.col.f32.tf32.tf32.f32 "
        "{%0,%1,%2,%3}, {%4,%5,%6,%7}, {%8,%9}, {%0,%1,%2,%3};\n"
        : "+f"(d[0]), "+f"(d[1]), "+f"(d[2]), "+f"(d[3])
        : "r"(a[0]), "r"(a[1]), "r"(a[2]), "r"(a[3]),
          "r"(b[0]), "r"(b[1]));
}

// ---------------------------------------------------------------------------
// GEMM 1: QKV = query @ w_qkv + b_qkv   (tf32x3 split: both operands hi/lo)
// 128x128x16 block tile, 8 warps (4x2), warp tile 32x64 (2x8 mma tiles)
// ---------------------------------------------------------------------------
__global__ __launch_bounds__(256) void gemm_qkv_mma(
    const float* __restrict__ A,      // [8192][1024]
    const float* __restrict__ Bw,     // [1024][3072]
    const float* __restrict__ bqkv)   // [3072]
{
    __shared__ __align__(16) unsigned Ah[128][20], Al[128][20];   // stride 20: conflict-free A-frag
    __shared__ __align__(16) unsigned Bh[16][136], Bl[16][136];   // stride 136: conflict-free B-frag

    const int K = HIDDEN, N = NQKV;
    const int bm = blockIdx.y * 128, bn = blockIdx.x * 128;
    const int tid = threadIdx.x, lane = tid & 31, wid = tid >> 5;
    const int grp = lane >> 2, tig = lane & 3;
    const int wm = (wid & 3) * 32, wn = (wid >> 2) * 64;
    const int ar = tid >> 2,  ac = (tid & 3) << 2;     // A tile: rows ar, ar+64
    const int br = tid >> 5,  bc = (tid & 31) << 2;    // B tile: rows br, br+8

    float acc[2][8][4];
#pragma unroll
    for (int i = 0; i < 2; i++)
#pragma unroll
        for (int j = 0; j < 8; j++)
#pragma unroll
            for (int c = 0; c < 4; c++) acc[i][j][c] = 0.f;

    // prologue: load + stage k0 = 0
    float4 ra0 = *(const float4*)&A[(bm + ar) * K + ac];
    float4 ra1 = *(const float4*)&A[(bm + ar + 64) * K + ac];
    float4 rb0 = *(const float4*)&Bw[br * N + bn + bc];
    float4 rb1 = *(const float4*)&Bw[(br + 8) * N + bn + bc];
    {
        uint4 hu, lu;
        cvt4(hu, lu, ra0); *(uint4*)&Ah[ar][ac] = hu;      *(uint4*)&Al[ar][ac] = lu;
        cvt4(hu, lu, ra1); *(uint4*)&Ah[ar + 64][ac] = hu; *(uint4*)&Al[ar + 64][ac] = lu;
        cvt4(hu, lu, rb0); *(uint4*)&Bh[br][bc] = hu;      *(uint4*)&Bl[br][bc] = lu;
        cvt4(hu, lu, rb1); *(uint4*)&Bh[br + 8][bc] = hu;  *(uint4*)&Bl[br + 8][bc] = lu;
    }
    __syncthreads();

    for (int k0 = 0; k0 < K; k0 += 16) {
        const bool more = (k0 + 16) < K;
        if (more) {
            ra0 = *(const float4*)&A[(bm + ar) * K + k0 + 16 + ac];
            ra1 = *(const float4*)&A[(bm + ar + 64) * K + k0 + 16 + ac];
            rb0 = *(const float4*)&Bw[(k0 + 16 + br) * N + bn + bc];
            rb1 = *(const float4*)&Bw[(k0 + 16 + br + 8) * N + bn + bc];
        }
#pragma unroll
        for (int kk = 0; kk < 16; kk += 8) {
            unsigned ah[2][4], al[2][4], bh[8][2], bl[8][2];
#pragma unroll
            for (int mt = 0; mt < 2; mt++) {
                int r = wm + mt * 16 + grp;
                ah[mt][0] = Ah[r][kk + tig];         al[mt][0] = Al[r][kk + tig];
                ah[mt][1] = Ah[r + 8][kk + tig];     al[mt][1] = Al[r + 8][kk + tig];
                ah[mt][2] = Ah[r][kk + tig + 4];     al[mt][2] = Al[r][kk + tig + 4];
                ah[mt][3] = Ah[r + 8][kk + tig + 4]; al[mt][3] = Al[r + 8][kk + tig + 4];
            }
#pragma unroll
            for (int nt = 0; nt < 8; nt++) {
                int c = wn + nt * 8 + grp;
                bh[nt][0] = Bh[kk + tig][c];     bl[nt][0] = Bl[kk + tig][c];
                bh[nt][1] = Bh[kk + tig + 4][c]; bl[nt][1] = Bl[kk + tig + 4][c];
            }
#pragma unroll
            for (int mt = 0; mt < 2; mt++)
#pragma unroll
                for (int nt = 0; nt < 8; nt++) {
                    mma8(acc[mt][nt], ah[mt], bh[nt]);
                    mma8(acc[mt][nt], ah[mt], bl[nt]);
                    mma8(acc[mt][nt], al[mt], bh[nt]);
                }
        }
        __syncthreads();
        if (more) {
            uint4 hu, lu;
            cvt4(hu, lu, ra0); *(uint4*)&Ah[ar][ac] = hu;      *(uint4*)&Al[ar][ac] = lu;
            cvt4(hu, lu, ra1); *(uint4*)&Ah[ar + 64][ac] = hu; *(uint4*)&Al[ar + 64][ac] = lu;
            cvt4(hu, lu, rb0); *(uint4*)&Bh[br][bc] = hu;      *(uint4*)&Bl[br][bc] = lu;
            cvt4(hu, lu, rb1); *(uint4*)&Bh[br + 8][bc] = hu;  *(uint4*)&Bl[br + 8][bc] = lu;
            __syncthreads();
        }
    }

    // epilogue: bias + head-split scatter; q pre-scaled by 0.125
#pragma unroll
    for (int mt = 0; mt < 2; mt++) {
#pragma unroll
        for (int cp = 0; cp < 2; cp++) {
            int m = bm + wm + mt * 16 + grp + cp * 8;
            int bb2 = m >> 11, ss = m & 2047;
#pragma unroll
            for (int nt = 0; nt < 8; nt++) {
#pragma unroll
                for (int cc = 0; cc < 2; cc++) {
                    int n = bn + wn + nt * 8 + 2 * tig + cc;
                    float v = acc[mt][nt][cp * 2 + cc] + bqkv[n];
                    int sec = n >> 10, nn = n & 1023;
                    int hh = nn >> 6, dd = nn & 63;
                    int idx = ((bb2 * HEADS + hh) * SEQ + ss) * HDIM + dd;
                    if (sec == 0)      g_q[idx] = v * 0.125f;
                    else if (sec == 1) g_k[idx] = v;
                    else               g_v[idx] = v;
                }
            }
        }
    }
}

// ---------------------------------------------------------------------------
// GEMM 2: out = g_ctx @ w_o + b_o   (split ctx operand only: 2 mma)
// ---------------------------------------------------------------------------
__global__ __launch_bounds__(256) void gemm_o_mma(
    const float* __restrict__ Bw,    // w_o [1024][1024]
    const float* __restrict__ bo,    // [1024]
    float* __restrict__ C)           // [8192][1024]
{
    __shared__ __align__(16) unsigned Ah[128][20], Al[128][20];
    __shared__ __align__(16) unsigned Bh[16][136];

    const int K = HIDDEN, N = HIDDEN;
    const int bm = blockIdx.y * 128, bn = blockIdx.x * 128;
    const int tid = threadIdx.x, lane = tid & 31, wid = tid >> 5;
    const int grp = lane >> 2, tig = lane & 3;
    const int wm = (wid & 3) * 32, wn = (wid >> 2) * 64;
    const int ar = tid >> 2,  ac = (tid & 3) << 2;
    const int br = tid >> 5,  bc = (tid & 31) << 2;

    float acc[2][8][4];
#pragma unroll
    for (int i = 0; i < 2; i++)
#pragma unroll
        for (int j = 0; j < 8; j++)
#pragma unroll
            for (int c = 0; c < 4; c++) acc[i][j][c] = 0.f;

    float4 ra0 = *(const float4*)&g_ctx[(bm + ar) * K + ac];
    float4 ra1 = *(const float4*)&g_ctx[(bm + ar + 64) * K + ac];
    float4 rb0 = *(const float4*)&Bw[br * N + bn + bc];
    float4 rb1 = *(const float4*)&Bw[(br + 8) * N + bn + bc];
    {
        uint4 hu, lu;
        cvt4(hu, lu, ra0); *(uint4*)&Ah[ar][ac] = hu;      *(uint4*)&Al[ar][ac] = lu;
        cvt4(hu, lu, ra1); *(uint4*)&Ah[ar + 64][ac] = hu; *(uint4*)&Al[ar + 64][ac] = lu;
        *(uint4*)&Bh[br][bc]     = cvt4s(rb0);
        *(uint4*)&Bh[br + 8][bc] = cvt4s(rb1);
    }
    __syncthreads();

    for (int k0 = 0; k0 < K; k0 += 16) {
        const bool more = (k0 + 16) < K;
        if (more) {
            ra0 = *(const float4*)&g_ctx[(bm + ar) * K + k0 + 16 + ac];
            ra1 = *(const float4*)&g_ctx[(bm + ar + 64) * K + k0 + 16 + ac];
            rb0 = *(const float4*)&Bw[(k0 + 16 + br) * N + bn + bc];
            rb1 = *(const float4*)&Bw[(k0 + 16 + br + 8) * N + bn + bc];
        }
#pragma unroll
        for (int kk = 0; kk < 16; kk += 8) {
            unsigned ah[2][4], al[2][4], bh[8][2];
#pragma unroll
            for (int mt = 0; mt < 2; mt++) {
                int r = wm + mt * 16 + grp;
                ah[mt][0] = Ah[r][kk + tig];         al[mt][0] = Al[r][kk + tig];
                ah[mt][1] = Ah[r + 8][kk + tig];     al[mt][1] = Al[r + 8][kk + tig];
                ah[mt][2] = Ah[r][kk + tig + 4];     al[mt][2] = Al[r][kk + tig + 4];
                ah[mt][3] = Ah[r + 8][kk + tig + 4]; al[mt][3] = Al[r + 8][kk + tig + 4];
            }
#pragma unroll
            for (int nt = 0; nt < 8; nt++) {
                int c = wn + nt * 8 + grp;
                bh[nt][0] = Bh[kk + tig][c];
                bh[nt][1] = Bh[kk + tig + 4][c];
            }
#pragma unroll
            for (int mt = 0; mt < 2; mt++)
#pragma unroll
                for (int nt = 0; nt < 8; nt++) {
                    mma8(acc[mt][nt], ah[mt], bh[nt]);
                    mma8(acc[mt][nt], al[mt], bh[nt]);
                }
        }
        __syncthreads();
        if (more) {
            uint4 hu, lu;
            cvt4(hu, lu, ra0); *(uint4*)&Ah[ar][ac] = hu;      *(uint4*)&Al[ar][ac] = lu;
            cvt4(hu, lu, ra1); *(uint4*)&Ah[ar + 64][ac] = hu; *(uint4*)&Al[ar + 64][ac] = lu;
            *(uint4*)&Bh[br][bc]     = cvt4s(rb0);
            *(uint4*)&Bh[br + 8][bc] = cvt4s(rb1);
            __syncthreads();
        }
    }

#pragma unroll
    for (int mt = 0; mt < 2; mt++) {
#pragma unroll
        for (int cp = 0; cp < 2; cp++) {
            int m = bm + wm + mt * 16 + grp + cp * 8;
#pragma unroll
            for (int nt = 0; nt < 8; nt++) {
                int n = bn + wn + nt * 8 + 2 * tig;
                float2 v;
                v.x = acc[mt][nt][cp * 2 + 0] + bo[n + 0];
                v.y = acc[mt][nt][cp * 2 + 1] + bo[n + 1];
                *(float2*)&C[m * N + n] = v;
            }
        }
    }
}

// ---------------------------------------------------------------------------
// Flash attention (tf32 mma): Br=128, Bc=32, d=64
// 8 warps x 16 rows; Q split hi/lo, K/V/P single tf32
// grid (SEQ/128, HEADS, BATCH), 256 threads, ~106 KB dynamic smem
// ---------------------------------------------------------------------------
#define FBR 128
#define FBC 32
#define QH_OFF 0
#define QL_OFF (128 * 68)
#define KS_OFF (2 * 128 * 68)
#define VS_OFF (2 * 128 * 68 + 32 * 68)
#define PS_OFF (2 * 128 * 68 + 32 * 68 + 32 * 72)
#define FLASH_SMEM ((2 * 128 * 68 + 32 * 68 + 32 * 72 + 128 * 36) * 4)

__global__ __launch_bounds__(256, 2) void flash_mma(const float* __restrict__ bias)
{
    extern __shared__ __align__(16) unsigned sm[];
    unsigned (*Qh)[68] = (unsigned(*)[68])(sm + QH_OFF);
    unsigned (*Ql)[68] = (unsigned(*)[68])(sm + QL_OFF);
    unsigned (*Ks)[68] = (unsigned(*)[68])(sm + KS_OFF);
    unsigned (*Vs)[72] = (unsigned(*)[72])(sm + VS_OFF);
    unsigned (*Ps)[36] = (unsigned(*)[36])(sm + PS_OFF);

    const int qt = blockIdx.x, h = blockIdx.y, b = blockIdx.z;
    const int tid = threadIdx.x, lane = tid & 31, wid = tid >> 5;
    const int grp = lane >> 2, tig = lane & 3;
    const int wr = wid * 16;                        // warp's 16 q-rows

    const float* qbase = g_q + ((b * HEADS + h) * SEQ + qt * FBR) * HDIM;
    const float* kbase = g_k + ((b * HEADS + h) * SEQ) * HDIM;
    const float* vbase = g_v + ((b * HEADS + h) * SEQ) * HDIM;

    // stage Q (128x64) -> hi/lo tf32
#pragma unroll
    for (int it = 0; it < 8; it++) {
        int id = tid + it * 256;           // 2048 float4 slots
        int r = id >> 4, c4 = (id & 15) << 2;
        float4 v = *(const float4*)&qbase[r * HDIM + c4];
        uint4 hu, lu;
        cvt4(hu, lu, v);
        *(uint4*)&Qh[r][c4] = hu;
        *(uint4*)&Ql[r][c4] = lu;
    }

    float o[8][4];
#pragma unroll
    for (int i = 0; i < 8; i++)
#pragma unroll
        for (int j = 0; j < 4; j++) o[i][j] = 0.f;
    float mr0 = -INFINITY, mr1 = -INFINITY, l0 = 0.f, l1 = 0.f;

    for (int kt = 0; kt < SEQ / FBC; kt++) {
        __syncthreads();   // Ks/Vs reuse safe (also orders Q staging on first iter)
#pragma unroll
        for (int it = 0; it < 2; it++) {   // K,V: 32x64 each = 512 float4 each
            int id = tid + it * 256;
            int r = id >> 4, c4 = (id & 15) << 2;
            float4 kv = *(const float4*)&kbase[(kt * FBC + r) * HDIM + c4];
            *(uint4*)&Ks[r][c4] = cvt4s(kv);
            float4 vv = *(const float4*)&vbase[(kt * FBC + r) * HDIM + c4];
            *(uint4*)&Vs[r][c4] = cvt4s(vv);
        }
        __syncthreads();

        // S = Q K^T : warp rows wr..wr+15, cols 0..31 (4 n-tiles)
        float s[4][4];
#pragma unroll
        for (int nt = 0; nt < 4; nt++)
#pragma unroll
            for (int c = 0; c < 4; c++) s[nt][c] = 0.f;
#pragma unroll
        for (int d0 = 0; d0 < HDIM; d0 += 8) {
            unsigned ah[4], al[4], bb[4][2];
            ah[0] = Qh[wr + grp][d0 + tig];         al[0] = Ql[wr + grp][d0 + tig];
            ah[1] = Qh[wr + grp + 8][d0 + tig];     al[1] = Ql[wr + grp + 8][d0 + tig];
            ah[2] = Qh[wr + grp][d0 + tig + 4];     al[2] = Ql[wr + grp][d0 + tig + 4];
            ah[3] = Qh[wr + grp + 8][d0 + tig + 4]; al[3] = Ql[wr + grp + 8][d0 + tig + 4];
#pragma unroll
            for (int nt = 0; nt < 4; nt++) {
                bb[nt][0] = Ks[nt * 8 + grp][d0 + tig];
                bb[nt][1] = Ks[nt * 8 + grp][d0 + tig + 4];
            }
#pragma unroll
            for (int nt = 0; nt < 4; nt++) {
                mma8(s[nt], ah, bb[nt]);
                mma8(s[nt], al, bb[nt]);
            }
        }

        // + bias
        const int qrow0 = qt * FBR + wr + grp;
#pragma unroll
        for (int nt = 0; nt < 4; nt++) {
            int kcol = kt * FBC + nt * 8 + 2 * tig;
            float2 bz0 = *(const float2*)&bias[qrow0 * SEQ + kcol];
            float2 bz1 = *(const float2*)&bias[(qrow0 + 8) * SEQ + kcol];
            s[nt][0] += bz0.x; s[nt][1] += bz0.y;
            s[nt][2] += bz1.x; s[nt][3] += bz1.y;
        }

        // online softmax (rows r0 = wr+grp, r1 = r0+8; 4 lanes/row share tig)
        float mx0 = s[0][0], mx1 = s[0][2];
#pragma unroll
        for (int nt = 0; nt < 4; nt++) {
            mx0 = fmaxf(mx0, fmaxf(s[nt][0], s[nt][1]));
            mx1 = fmaxf(mx1, fmaxf(s[nt][2], s[nt][3]));
        }
        mx0 = fmaxf(mx0, __shfl_xor_sync(0xffffffffu, mx0, 1));
        mx0 = fmaxf(mx0, __shfl_xor_sync(0xffffffffu, mx0, 2));
        mx1 = fmaxf(mx1, __shfl_xor_sync(0xffffffffu, mx1, 1));
        mx1 = fmaxf(mx1, __shfl_xor_sync(0xffffffffu, mx1, 2));
        float nm0 = fmaxf(mr0, mx0), nm1 = fmaxf(mr1, mx1);
        float al0 = __expf(mr0 - nm0), al1 = __expf(mr1 - nm1);
        mr0 = nm0; mr1 = nm1;
        float sum0 = 0.f, sum1 = 0.f;
#pragma unroll
        for (int nt = 0; nt < 4; nt++) {
            s[nt][0] = __expf(s[nt][0] - nm0);
            s[nt][1] = __expf(s[nt][1] - nm0);
            s[nt][2] = __expf(s[nt][2] - nm1);
            s[nt][3] = __expf(s[nt][3] - nm1);
            sum0 += s[nt][0] + s[nt][1];
            sum1 += s[nt][2] + s[nt][3];
        }
        sum0 += __shfl_xor_sync(0xffffffffu, sum0, 1);
        sum0 += __shfl_xor_sync(0xffffffffu, sum0, 2);
        sum1 += __shfl_xor_sync(0xffffffffu, sum1, 1);
        sum1 += __shfl_xor_sync(0xffffffffu, sum1, 2);
        l0 = l0 * al0 + sum0;
        l1 = l1 * al1 + sum1;
#pragma unroll
        for (int nt = 0; nt < 8; nt++) {
            o[nt][0] *= al0; o[nt][1] *= al0;
            o[nt][2] *= al1; o[nt][3] *= al1;
        }

        // stage P (warp-local) as tf32
#pragma unroll
        for (int nt = 0; nt < 4; nt++) {
            uint2 u0, u1;
            u0.x = f2tf(s[nt][0]); u0.y = f2tf(s[nt][1]);
            u1.x = f2tf(s[nt][2]); u1.y = f2tf(s[nt][3]);
            *(uint2*)&Ps[wr + grp][nt * 8 + 2 * tig]     = u0;
            *(uint2*)&Ps[wr + grp + 8][nt * 8 + 2 * tig] = u1;
        }
        __syncwarp();

        // O += P V  (warp rows wr..wr+15, 8 n-tiles over d=64)
#pragma unroll
        for (int kc = 0; kc < FBC; kc += 8) {
            unsigned a[4], bv[8][2];
            a[0] = Ps[wr + grp][kc + tig];
            a[1] = Ps[wr + grp + 8][kc + tig];
            a[2] = Ps[wr + grp][kc + tig + 4];
            a[3] = Ps[wr + grp + 8][kc + tig + 4];
#pragma unroll
            for (int nt = 0; nt < 8; nt++) {
                bv[nt][0] = Vs[kc + tig][nt * 8 + grp];
                bv[nt][1] = Vs[kc + tig + 4][nt * 8 + grp];
            }
#pragma unroll
            for (int nt = 0; nt < 8; nt++)
                mma8(o[nt], a, bv[nt]);
        }
    }

    // epilogue: normalize, write ctx [b][s][h][d]
    const float i0 = 1.f / l0, i1 = 1.f / l1;
    const int s0 = qt * FBR + wr + grp;
    const int base0 = ((b * SEQ + s0) * HEADS + h) * HDIM;
    const int base1 = ((b * SEQ + s0 + 8) * HEADS + h) * HDIM;
#pragma unroll
    for (int nt = 0; nt < 8; nt++) {
        int d = nt * 8 + 2 * tig;
        *(float2*)&g_ctx[base0 + d] = make_float2(o[nt][0] * i0, o[nt][1] * i0);
        *(float2*)&g_ctx[base1 + d] = make_float2(o[nt][2] * i1, o[nt][3] * i1);
    }
}

// ---------------------------------------------------------------------------
extern "C" void kernel_launch(void* const* d_in, const int* in_sizes, int n_in,
                              void* d_out, int out_size)
{
    const float* query = (const float*)d_in[0];
    const float* bias  = (const float*)d_in[1];
    const float* w_qkv = (const float*)d_in[2];
    const float* b_qkv = (const float*)d_in[3];
    const float* w_o   = (const float*)d_in[4];
    const float* b_o   = (const float*)d_in[5];
    float* out = (float*)d_out;

    cudaFuncSetAttribute(flash_mma, cudaFuncAttributeMaxDynamicSharedMemorySize,
                         FLASH_SMEM);

    dim3 g1(NQKV / 128, MROWS / 128);        // 24 x 64
    gemm_qkv_mma<<<g1, 256>>>(query, w_qkv, b_qkv);

    dim3 gf(SEQ / FBR, HEADS, BATCH);        // 16 x 16 x 4
    flash_mma<<<gf, 256, FLASH_SMEM>>>(bias);

    dim3 g2(HIDDEN / 128, MROWS / 128);      // 8 x 64
    gemm_o_mma<<<g2, 256>>>(w_o, b_o, out);
}